// round 14
// baseline (speedup 1.0000x reference)
#include <cuda_runtime.h>
#include <cuda_fp16.h>
#include <cstdint>
#include <math.h>

// ============================================================================
// DUQ head via HMMA 3xFP16-split GEMM — R9 pipeline made PERSISTENT.
// out[b,c,p] = exp(-3.125 * sum_e (emb[p, c*16+e] - cent[c*16+e])^2)
// emb = feat[b,:,p].w[n,:], n=c*16+e, K=512.
// a = ah+al, b = bh+bl (exact fp16 splits); acc += ah*bh + ah*bl + al*bh (f32).
// Persistent grid G = 2*SMs (floored to %8==0); CTA walks tiles tid += G.
// G%8==0 -> nb = ctaid&7 constant per CTA: cent loaded once, B L2-hot.
// cp.async pipeline runs continuously ACROSS tiles (kt=14/15 fill next tile's
// kt=0/1), so epilogues overlap in-flight loads and CTAs never re-prime.
// CTA tile 128x128, warp tile 32x64, BK=32, 3 stages, 96KB smem, 2 CTAs/SM.
// ============================================================================

#define BM 128
#define BN 128
#define BK 32
#define KTILES 16
#define NTILES 8192          // (131072/128) * (1024/128)
#define STAGE_BYTES 32768    // Ahi 8K | Alo 8K | Bhi 8K | Blo 8K
#define OFF_ALO 8192
#define OFF_BHI 16384
#define OFF_BLO 24576
#define CENT_OFF (3 * STAGE_BYTES)
#define SMEM_TOTAL (CENT_OFF + 512)

// -------- device-global scratch (no cudaMalloc allowed) ----------------------
__device__ __half g_ah[67108864];   // [131072 px][512 k]
__device__ __half g_al[67108864];
__device__ __half g_bh[524288];     // [1024 n][512 k], n = c*16+e
__device__ __half g_bl[524288];
__device__ float  g_cent[1024];

// -------- helpers -------------------------------------------------------------
__device__ __forceinline__ uint32_t smem_u32(const void* p) {
    uint32_t a;
    asm("{ .reg .u64 t; cvta.to.shared.u64 t, %1; cvt.u32.u64 %0, t; }" : "=r"(a) : "l"(p));
    return a;
}
__device__ __forceinline__ void cp16(uint32_t dst, const __half* src) {
    asm volatile("cp.async.cg.shared.global [%0], [%1], 16;"
                 :: "r"(dst), "l"(__cvta_generic_to_global(src)));
}
__device__ __forceinline__ void ldsm4(uint32_t* r, uint32_t addr) {
    asm volatile("ldmatrix.sync.aligned.m8n8.x4.shared.b16 {%0,%1,%2,%3}, [%4];"
                 : "=r"(r[0]), "=r"(r[1]), "=r"(r[2]), "=r"(r[3]) : "r"(addr));
}
__device__ __forceinline__ void mma_f32(float* c, const uint32_t* a, const uint32_t* b) {
    asm volatile("mma.sync.aligned.m16n8k16.row.col.f32.f16.f16.f32 "
                 "{%0,%1,%2,%3}, {%4,%5,%6,%7}, {%8,%9}, {%0,%1,%2,%3};"
                 : "+f"(c[0]), "+f"(c[1]), "+f"(c[2]), "+f"(c[3])
                 : "r"(a[0]), "r"(a[1]), "r"(a[2]), "r"(a[3]), "r"(b[0]), "r"(b[1]));
}

// -------- prep 1: transpose + fp16-split features (R9 version) ----------------
__global__ void prep_feat(const float* __restrict__ feat) {
    __shared__ float tile[32][65];     // [p][k], padded
    int b  = blockIdx.z;
    int p0 = blockIdx.x * 32, k0 = blockIdx.y * 64;
    int tx = threadIdx.x, ty = threadIdx.y;                // (32, 8)
    const float* src = feat + ((size_t)b * 512 + k0) * 16384 + p0;
#pragma unroll
    for (int i = 0; i < 8; i++) {
        int kr = ty + 8 * i;
        tile[tx][kr] = src[(size_t)kr * 16384 + tx];
    }
    __syncthreads();
    size_t dbase = ((size_t)b * 16384 + p0) * 512 + k0;
#pragma unroll
    for (int j = 0; j < 4; j++) {
        int pr = ty + 8 * j;
        float v0 = tile[pr][2 * tx];
        float v1 = tile[pr][2 * tx + 1];
        __half h0 = __float2half_rn(v0);
        __half h1 = __float2half_rn(v1);
        __half l0 = __float2half_rn(v0 - __half2float(h0));
        __half l1 = __float2half_rn(v1 - __half2float(h1));
        size_t off = dbase + (size_t)pr * 512 + 2 * tx;
        *(__half2*)(g_ah + off) = __halves2half2(h0, h1);
        *(__half2*)(g_al + off) = __halves2half2(l0, l1);
    }
}

// -------- prep 2: weights reorder + split, centroids --------------------------
__global__ void prep_w(const float* __restrict__ wgt, const float* __restrict__ m,
                       const float* __restrict__ Nb) {
    int n = blockIdx.x;                 // n = c*16 + e
    int c = n >> 4, e = n & 15;
    const float* src = wgt + ((size_t)e * 64 + c) * 512;
    for (int k = threadIdx.x; k < 512; k += 128) {
        float v = src[k];
        __half hi = __float2half_rn(v);
        g_bh[(size_t)n * 512 + k] = hi;
        g_bl[(size_t)n * 512 + k] = __float2half_rn(v - __half2float(hi));
    }
    if (threadIdx.x == 0) g_cent[n] = m[e * 64 + c] / Nb[c];
}

// -------- stage fill (256 threads): 8 x 16B cp.async per thread ----------------
__device__ __forceinline__ void fill_stage(uint32_t sb, int s, int kt, long P0, int n0, int t) {
    int kb = kt * BK;
    uint32_t st = sb + s * STAGE_BYTES;
    int r = t >> 2, c = t & 3;
#pragma unroll
    for (int i = 0; i < 2; i++) {
        int rr = r + i * 64;
        uint32_t d = st + rr * 64 + (uint32_t)((c ^ ((rr >> 1) & 3)) << 4);
        size_t asrc = (size_t)(P0 + rr) * 512 + kb + c * 8;
        size_t bsrc = (size_t)(n0 + rr) * 512 + kb + c * 8;
        cp16(d,           g_ah + asrc);
        cp16(d + OFF_ALO, g_al + asrc);
        cp16(d + OFF_BHI, g_bh + bsrc);
        cp16(d + OFF_BLO, g_bl + bsrc);
    }
}

// -------- main persistent GEMM + fused RBF epilogue ----------------------------
__global__ __launch_bounds__(256, 2) void duq_mma(float* __restrict__ out, int G) {
    extern __shared__ char smem[];
    uint32_t sb = smem_u32(smem);
    int t = threadIdx.x, l = t & 31, w = t >> 5;
    int ctaid = blockIdx.x;
    int nb = ctaid & 7;                // constant across this CTA's tiles (G%8==0)
    int n0 = nb * BN;

    if (t < BN) ((float*)(smem + CENT_OFF))[t] = g_cent[n0 + t];

    int wm = (w >> 1) * 32;            // 4 M-groups of 32
    int wn = (w & 1) * 64;             // 2 N-groups of 64

    int rl  = l & 7;
    int mh  = (l >> 3) & 1;
    int hi  = (l >> 4) & 1;

    const float* centS = (const float*)(smem + CENT_OFF);
    int q2 = l & 3;
    int cb = (n0 + wn) >> 4;

    if (ctaid >= NTILES) return;

    // prime pipeline with first tile's kt=0,1
    {
        long P0f = (long)(ctaid >> 3) << 7;
        fill_stage(sb, 0, 0, P0f, n0, t);
        asm volatile("cp.async.commit_group;" ::: "memory");
        fill_stage(sb, 1, 1, P0f, n0, t);
        asm volatile("cp.async.commit_group;" ::: "memory");
    }

    int cs = 0;                         // consume stage (continuous across tiles)
    for (long tid = ctaid; tid < NTILES; tid += G) {
        long P0  = (tid >> 3) << 7;
        long tid2 = tid + G;
        long P0n = (tid2 >> 3) << 7;
        int have_next = (tid2 < NTILES);

        float acc[2][8][4];
#pragma unroll
        for (int i = 0; i < 2; i++)
#pragma unroll
            for (int j = 0; j < 8; j++)
#pragma unroll
                for (int q = 0; q < 4; q++) acc[i][j][q] = 0.0f;

        for (int kt = 0; kt < KTILES; kt++) {
            asm volatile("cp.async.wait_group 1;" ::: "memory");
            __syncthreads();

            int fs = cs + 2; if (fs >= 3) fs -= 3;
            if (kt < KTILES - 2)
                fill_stage(sb, fs, kt + 2, P0, n0, t);
            else if (have_next)
                fill_stage(sb, fs, kt - (KTILES - 2), P0n, n0, t);
            asm volatile("cp.async.commit_group;" ::: "memory");

            uint32_t As = sb + cs * STAGE_BYTES;
#pragma unroll
            for (int k16 = 0; k16 < 2; k16++) {
                uint32_t ah[2][4], al[2][4];
#pragma unroll
                for (int mf = 0; mf < 2; mf++) {
                    int ra = wm + mf * 16 + mh * 8 + rl;
                    uint32_t off = (uint32_t)(ra * 64 + (((2 * k16 + hi) ^ ((ra >> 1) & 3)) << 4));
                    ldsm4(ah[mf], As + off);
                    ldsm4(al[mf], As + OFF_ALO + off);
                }
#pragma unroll
                for (int np = 0; np < 4; np++) {
                    int rb = wn + np * 16 + hi * 8 + rl;
                    uint32_t off = (uint32_t)(rb * 64 + (((2 * k16 + mh) ^ ((rb >> 1) & 3)) << 4));
                    uint32_t bh4[4], bl4[4];
                    ldsm4(bh4, As + OFF_BHI + off);
                    ldsm4(bl4, As + OFF_BLO + off);
#pragma unroll
                    for (int mf = 0; mf < 2; mf++)
#pragma unroll
                        for (int h = 0; h < 2; h++)
                            mma_f32(acc[mf][2 * np + h], ah[mf], &bh4[2 * h]);
#pragma unroll
                    for (int mf = 0; mf < 2; mf++)
#pragma unroll
                        for (int h = 0; h < 2; h++)
                            mma_f32(acc[mf][2 * np + h], ah[mf], &bl4[2 * h]);
#pragma unroll
                    for (int mf = 0; mf < 2; mf++)
#pragma unroll
                        for (int h = 0; h < 2; h++)
                            mma_f32(acc[mf][2 * np + h], al[mf], &bh4[2 * h]);
                }
            }
            cs = (cs == 2) ? 0 : cs + 1;
        }

        // ---- per-tile epilogue (next tile's loads already in flight) ----
#pragma unroll
        for (int mf = 0; mf < 2; mf++) {
            float s[4][2];
#pragma unroll
            for (int ch = 0; ch < 4; ch++) { s[ch][0] = 0.0f; s[ch][1] = 0.0f; }
#pragma unroll
            for (int nf = 0; nf < 8; nf++) {
                int ch = nf >> 1;
#pragma unroll
                for (int j = 0; j < 2; j++) {
                    float ce = centS[wn + nf * 8 + 2 * q2 + j];
                    float d0 = acc[mf][nf][j]     - ce;
                    float d1 = acc[mf][nf][2 + j] - ce;
                    s[ch][0] = fmaf(d0, d0, s[ch][0]);
                    s[ch][1] = fmaf(d1, d1, s[ch][1]);
                }
            }
#pragma unroll
            for (int ch = 0; ch < 4; ch++)
#pragma unroll
                for (int r = 0; r < 2; r++) {
                    s[ch][r] += __shfl_xor_sync(0xFFFFFFFFu, s[ch][r], 1);
                    s[ch][r] += __shfl_xor_sync(0xFFFFFFFFu, s[ch][r], 2);
                }
            float v0 = (q2 == 0) ? s[0][0] : (q2 == 1) ? s[1][0] : (q2 == 2) ? s[2][0] : s[3][0];
            float v1 = (q2 == 0) ? s[0][1] : (q2 == 1) ? s[1][1] : (q2 == 2) ? s[2][1] : s[3][1];

            long gp = P0 + wm + mf * 16 + (l >> 2);
            int b   = (int)(gp >> 14);
            int pin = (int)(gp & 16383);
            int ch  = cb + q2;
            float* o = out + ((size_t)b * 64 + ch) * 16384 + pin;
            o[0] = __expf(-3.125f * v0);
            o[8] = __expf(-3.125f * v1);
        }
    }
}

// -------- launch ----------------------------------------------------------------
extern "C" void kernel_launch(void* const* d_in, const int* in_sizes, int n_in,
                              void* d_out, int out_size)
{
    const float* feat = (const float*)d_in[0];   // [8, 512, 128, 128]
    const float* wgt  = (const float*)d_in[1];   // [16, 64, 512]
    const float* m    = (const float*)d_in[2];   // [16, 64]
    const float* N    = (const float*)d_in[3];   // [64]
    float* out        = (float*)d_out;           // [8, 64, 128, 128]

    int sm = 0;
    cudaDeviceGetAttribute(&sm, cudaDevAttrMultiProcessorCount, 0);
    int G = (2 * sm) & ~7;              // persistent grid, multiple of 8
    if (G < 8) G = 8;
    if (G > NTILES) G = NTILES;

    cudaFuncSetAttribute(duq_mma, cudaFuncAttributeMaxDynamicSharedMemorySize, SMEM_TOTAL);

    prep_feat<<<dim3(512, 8, 8), dim3(32, 8)>>>(feat);
    prep_w<<<1024, 128>>>(wgt, m, N);
    duq_mma<<<G, 256, SMEM_TOTAL>>>(out, G);
}

// round 15
// speedup vs baseline: 1.0038x; 1.0038x over previous
#include <cuda_runtime.h>
#include <cuda_fp16.h>
#include <cstdint>
#include <math.h>

// ============================================================================
// DUQ head via HMMA 3xFP16-split GEMM — R9 pipeline, 64x64 warp tile,
// 128-thread CTAs (2 CTAs/SM -> 256 regs/thread budget).
// out[b,c,p] = exp(-3.125 * sum_e (emb[p, c*16+e] - cent[c*16+e])^2)
// emb = feat[b,:,p].w[n,:], n=c*16+e, K=512.
// a = ah+al, b = bh+bl (exact fp16 splits); acc += ah*bh + ah*bl + al*bh (f32).
// Per warp per k-tile: 192 MMAs vs ~80 non-MMA issues -> tensor-pipe bound
// (R9's 32x64 warp tile was issue-bound at 48 MMA vs ~62 non-MMA).
// CTA tile 128x128, 4 warps (2x2 of 64x64), BK=32, 3-stage cp.async,
// 96KB smem, 2 CTAs/SM.
// ============================================================================

#define BM 128
#define BN 128
#define BK 32
#define KTILES 16            // 512 / 32
#define STAGE_BYTES 32768    // Ahi 8K | Alo 8K | Bhi 8K | Blo 8K
#define OFF_ALO 8192
#define OFF_BHI 16384
#define OFF_BLO 24576
#define CENT_OFF (3 * STAGE_BYTES)
#define SMEM_TOTAL (CENT_OFF + 512)

// -------- device-global scratch (no cudaMalloc allowed) ----------------------
__device__ __half g_ah[67108864];   // [131072 px][512 k]
__device__ __half g_al[67108864];
__device__ __half g_bh[524288];     // [1024 n][512 k], n = c*16+e
__device__ __half g_bl[524288];
__device__ float  g_cent[1024];

// -------- helpers -------------------------------------------------------------
__device__ __forceinline__ uint32_t smem_u32(const void* p) {
    uint32_t a;
    asm("{ .reg .u64 t; cvta.to.shared.u64 t, %1; cvt.u32.u64 %0, t; }" : "=r"(a) : "l"(p));
    return a;
}
__device__ __forceinline__ void cp16(uint32_t dst, const __half* src) {
    asm volatile("cp.async.cg.shared.global [%0], [%1], 16;"
                 :: "r"(dst), "l"(__cvta_generic_to_global(src)));
}
__device__ __forceinline__ void ldsm4(uint32_t* r, uint32_t addr) {
    asm volatile("ldmatrix.sync.aligned.m8n8.x4.shared.b16 {%0,%1,%2,%3}, [%4];"
                 : "=r"(r[0]), "=r"(r[1]), "=r"(r[2]), "=r"(r[3]) : "r"(addr));
}
__device__ __forceinline__ void mma_f32(float* c, const uint32_t* a, const uint32_t* b) {
    asm volatile("mma.sync.aligned.m16n8k16.row.col.f32.f16.f16.f32 "
                 "{%0,%1,%2,%3}, {%4,%5,%6,%7}, {%8,%9}, {%0,%1,%2,%3};"
                 : "+f"(c[0]), "+f"(c[1]), "+f"(c[2]), "+f"(c[3])
                 : "r"(a[0]), "r"(a[1]), "r"(a[2]), "r"(a[3]), "r"(b[0]), "r"(b[1]));
}

// -------- prep 1: transpose + fp16-split features -----------------------------
__global__ void prep_feat(const float* __restrict__ feat) {
    __shared__ float tile[32][65];     // [p][k], padded
    int b  = blockIdx.z;
    int p0 = blockIdx.x * 32, k0 = blockIdx.y * 64;
    int tx = threadIdx.x, ty = threadIdx.y;                // (32, 8)
    const float* src = feat + ((size_t)b * 512 + k0) * 16384 + p0;
#pragma unroll
    for (int i = 0; i < 8; i++) {
        int kr = ty + 8 * i;
        tile[tx][kr] = src[(size_t)kr * 16384 + tx];
    }
    __syncthreads();
    size_t dbase = ((size_t)b * 16384 + p0) * 512 + k0;
#pragma unroll
    for (int j = 0; j < 4; j++) {
        int pr = ty + 8 * j;
        float v0 = tile[pr][2 * tx];
        float v1 = tile[pr][2 * tx + 1];
        __half h0 = __float2half_rn(v0);
        __half h1 = __float2half_rn(v1);
        __half l0 = __float2half_rn(v0 - __half2float(h0));
        __half l1 = __float2half_rn(v1 - __half2float(h1));
        size_t off = dbase + (size_t)pr * 512 + 2 * tx;
        *(__half2*)(g_ah + off) = __halves2half2(h0, h1);
        *(__half2*)(g_al + off) = __halves2half2(l0, l1);
    }
}

// -------- prep 2: weights reorder + split, centroids --------------------------
__global__ void prep_w(const float* __restrict__ wgt, const float* __restrict__ m,
                       const float* __restrict__ Nb) {
    int n = blockIdx.x;                 // n = c*16 + e
    int c = n >> 4, e = n & 15;
    const float* src = wgt + ((size_t)e * 64 + c) * 512;
    for (int k = threadIdx.x; k < 512; k += 128) {
        float v = src[k];
        __half hi = __float2half_rn(v);
        g_bh[(size_t)n * 512 + k] = hi;
        g_bl[(size_t)n * 512 + k] = __float2half_rn(v - __half2float(hi));
    }
    if (threadIdx.x == 0) g_cent[n] = m[e * 64 + c] / Nb[c];
}

// -------- stage fill (128 threads): 16 x 16B cp.async per thread ---------------
// 64B rows (4 chunks of 16B), swizzle chunk ^ ((row>>1)&3) -> ldsm conflict-free
__device__ __forceinline__ void fill_stage(uint32_t sb, int s, int kt, long P0, int n0, int t) {
    int kb = kt * BK;
    uint32_t st = sb + s * STAGE_BYTES;
    int r = t >> 2, c = t & 3;          // r: 0..31
#pragma unroll
    for (int i = 0; i < 4; i++) {
        int rr = r + i * 32;
        uint32_t d = st + rr * 64 + (uint32_t)((c ^ ((rr >> 1) & 3)) << 4);
        size_t asrc = (size_t)(P0 + rr) * 512 + kb + c * 8;
        size_t bsrc = (size_t)(n0 + rr) * 512 + kb + c * 8;
        cp16(d,           g_ah + asrc);
        cp16(d + OFF_ALO, g_al + asrc);
        cp16(d + OFF_BHI, g_bh + bsrc);
        cp16(d + OFF_BLO, g_bl + bsrc);
    }
}

// -------- main GEMM + fused RBF epilogue ---------------------------------------
__global__ __launch_bounds__(128, 2) void duq_mma(float* __restrict__ out) {
    extern __shared__ char smem[];
    uint32_t sb = smem_u32(smem);
    int t = threadIdx.x, l = t & 31, w = t >> 5;   // 4 warps
    int nb = blockIdx.x, mb = blockIdx.y;
    long P0 = (long)mb * BM;           // 128 | 16384 -> never crosses a batch
    int n0 = nb * BN;

    ((float*)(smem + CENT_OFF))[t] = g_cent[n0 + t];   // 128 threads = BN

    int wm = (w >> 1) * 64;            // 2 M-groups of 64
    int wn = (w & 1) * 64;             // 2 N-groups of 64

    int rl  = l & 7;                   // row within 8-row matrix
    int mh  = (l >> 3) & 1;            // matrix half bit
    int hi  = (l >> 4) & 1;            // k-chunk bit

    float acc[4][8][4];                // 64x64 warp tile
#pragma unroll
    for (int i = 0; i < 4; i++)
#pragma unroll
        for (int j = 0; j < 8; j++)
#pragma unroll
            for (int q = 0; q < 4; q++) acc[i][j][q] = 0.0f;

    fill_stage(sb, 0, 0, P0, n0, t);
    asm volatile("cp.async.commit_group;" ::: "memory");
    fill_stage(sb, 1, 1, P0, n0, t);
    asm volatile("cp.async.commit_group;" ::: "memory");

    for (int kt = 0; kt < KTILES; kt++) {
        asm volatile("cp.async.wait_group 1;" ::: "memory");
        __syncthreads();

        if (kt + 2 < KTILES) fill_stage(sb, (kt + 2) % 3, kt + 2, P0, n0, t);
        asm volatile("cp.async.commit_group;" ::: "memory");

        uint32_t As = sb + (kt % 3) * STAGE_BYTES;
#pragma unroll
        for (int k16 = 0; k16 < 2; k16++) {
            uint32_t ah[4][4], al[4][4];
#pragma unroll
            for (int mf = 0; mf < 4; mf++) {
                int ra = wm + mf * 16 + mh * 8 + rl;
                uint32_t off = (uint32_t)(ra * 64 + (((2 * k16 + hi) ^ ((ra >> 1) & 3)) << 4));
                ldsm4(ah[mf], As + off);
                ldsm4(al[mf], As + OFF_ALO + off);
            }
#pragma unroll
            for (int np = 0; np < 4; np++) {
                int rb = wn + np * 16 + hi * 8 + rl;
                uint32_t off = (uint32_t)(rb * 64 + (((2 * k16 + mh) ^ ((rb >> 1) & 3)) << 4));
                uint32_t bh4[4], bl4[4];
                ldsm4(bh4, As + OFF_BHI + off);
                ldsm4(bl4, As + OFF_BLO + off);
                // product-major: 8 independent MMAs per product group
#pragma unroll
                for (int mf = 0; mf < 4; mf++)
#pragma unroll
                    for (int h = 0; h < 2; h++)
                        mma_f32(acc[mf][2 * np + h], ah[mf], &bh4[2 * h]);
#pragma unroll
                for (int mf = 0; mf < 4; mf++)
#pragma unroll
                    for (int h = 0; h < 2; h++)
                        mma_f32(acc[mf][2 * np + h], ah[mf], &bl4[2 * h]);
#pragma unroll
                for (int mf = 0; mf < 4; mf++)
#pragma unroll
                    for (int h = 0; h < 2; h++)
                        mma_f32(acc[mf][2 * np + h], al[mf], &bh4[2 * h]);
            }
        }
    }

    // ---- epilogue: diff^2, 16-e reduction (2 quad shuffles), __expf, store ----
    const float* centS = (const float*)(smem + CENT_OFF);
    int q2 = l & 3;
    int cb = (n0 + wn) >> 4;           // first of this warp's 4 channels

#pragma unroll
    for (int mf = 0; mf < 4; mf++) {
        float s[4][2];
#pragma unroll
        for (int ch = 0; ch < 4; ch++) { s[ch][0] = 0.0f; s[ch][1] = 0.0f; }
#pragma unroll
        for (int nf = 0; nf < 8; nf++) {
            int ch = nf >> 1;
#pragma unroll
            for (int j = 0; j < 2; j++) {
                float ce = centS[wn + nf * 8 + 2 * q2 + j];
                float d0 = acc[mf][nf][j]     - ce;
                float d1 = acc[mf][nf][2 + j] - ce;
                s[ch][0] = fmaf(d0, d0, s[ch][0]);
                s[ch][1] = fmaf(d1, d1, s[ch][1]);
            }
        }
#pragma unroll
        for (int ch = 0; ch < 4; ch++)
#pragma unroll
            for (int r = 0; r < 2; r++) {
                s[ch][r] += __shfl_xor_sync(0xFFFFFFFFu, s[ch][r], 1);
                s[ch][r] += __shfl_xor_sync(0xFFFFFFFFu, s[ch][r], 2);
            }
        float v0 = (q2 == 0) ? s[0][0] : (q2 == 1) ? s[1][0] : (q2 == 2) ? s[2][0] : s[3][0];
        float v1 = (q2 == 0) ? s[0][1] : (q2 == 1) ? s[1][1] : (q2 == 2) ? s[2][1] : s[3][1];

        long gp = P0 + wm + mf * 16 + (l >> 2);
        int b   = (int)(gp >> 14);
        int pin = (int)(gp & 16383);
        int ch  = cb + q2;
        float* o = out + ((size_t)b * 64 + ch) * 16384 + pin;
        o[0] = __expf(-3.125f * v0);
        o[8] = __expf(-3.125f * v1);
    }
}

// -------- launch ----------------------------------------------------------------
extern "C" void kernel_launch(void* const* d_in, const int* in_sizes, int n_in,
                              void* d_out, int out_size)
{
    const float* feat = (const float*)d_in[0];   // [8, 512, 128, 128]
    const float* wgt  = (const float*)d_in[1];   // [16, 64, 512]
    const float* m    = (const float*)d_in[2];   // [16, 64]
    const float* N    = (const float*)d_in[3];   // [64]
    float* out        = (float*)d_out;           // [8, 64, 128, 128]

    cudaFuncSetAttribute(duq_mma, cudaFuncAttributeMaxDynamicSharedMemorySize, SMEM_TOTAL);

    prep_feat<<<dim3(512, 8, 8), dim3(32, 8)>>>(feat);
    prep_w<<<1024, 128>>>(wgt, m, N);
    duq_mma<<<dim3(8, 1024), 128, SMEM_TOTAL>>>(out);
}

// round 16
// speedup vs baseline: 1.0449x; 1.0409x over previous
#include <cuda_runtime.h>
#include <cuda_fp16.h>
#include <cstdint>
#include <math.h>

// ============================================================================
// DUQ head via HMMA 3xFP16-split GEMM — R9 configuration (best known) with
// streaming cache hints in the prep kernels.
// out[b,c,p] = exp(-3.125 * sum_e (emb[p, c*16+e] - cent[c*16+e])^2)
// emb = feat[b,:,p].w[n,:], n=c*16+e, K=512.
// a = ah+al, b = bh+bl (exact fp16 splits); acc += ah*bh + ah*bl + al*bh (f32).
// CTA tile 128x128, warp tile 32x64 (8 warps/256 thr), BK=32,
// 3-stage cp.async, 96KB smem, 2 CTAs/SM.
// ============================================================================

#define BM 128
#define BN 128
#define BK 32
#define KTILES 16            // 512 / 32
#define STAGE_BYTES 32768    // Ahi 8K | Alo 8K | Bhi 8K | Blo 8K
#define OFF_ALO 8192
#define OFF_BHI 16384
#define OFF_BLO 24576
#define CENT_OFF (3 * STAGE_BYTES)
#define SMEM_TOTAL (CENT_OFF + 512)

// -------- device-global scratch (no cudaMalloc allowed) ----------------------
__device__ __half g_ah[67108864];   // [131072 px][512 k]
__device__ __half g_al[67108864];
__device__ __half g_bh[524288];     // [1024 n][512 k], n = c*16+e
__device__ __half g_bl[524288];
__device__ float  g_cent[1024];

// -------- helpers -------------------------------------------------------------
__device__ __forceinline__ uint32_t smem_u32(const void* p) {
    uint32_t a;
    asm("{ .reg .u64 t; cvta.to.shared.u64 t, %1; cvt.u32.u64 %0, t; }" : "=r"(a) : "l"(p));
    return a;
}
__device__ __forceinline__ void cp16(uint32_t dst, const __half* src) {
    asm volatile("cp.async.cg.shared.global [%0], [%1], 16;"
                 :: "r"(dst), "l"(__cvta_generic_to_global(src)));
}
__device__ __forceinline__ void ldsm4(uint32_t* r, uint32_t addr) {
    asm volatile("ldmatrix.sync.aligned.m8n8.x4.shared.b16 {%0,%1,%2,%3}, [%4];"
                 : "=r"(r[0]), "=r"(r[1]), "=r"(r[2]), "=r"(r[3]) : "r"(addr));
}
__device__ __forceinline__ void mma_f32(float* c, const uint32_t* a, const uint32_t* b) {
    asm volatile("mma.sync.aligned.m16n8k16.row.col.f32.f16.f16.f32 "
                 "{%0,%1,%2,%3}, {%4,%5,%6,%7}, {%8,%9}, {%0,%1,%2,%3};"
                 : "+f"(c[0]), "+f"(c[1]), "+f"(c[2]), "+f"(c[3])
                 : "r"(a[0]), "r"(a[1]), "r"(a[2]), "r"(a[3]), "r"(b[0]), "r"(b[1]));
}

// -------- prep 1: transpose + fp16-split features (streaming hints) -----------
__global__ void prep_feat(const float* __restrict__ feat) {
    __shared__ float tile[32][65];     // [p][k], padded
    int b  = blockIdx.z;
    int p0 = blockIdx.x * 32, k0 = blockIdx.y * 64;
    int tx = threadIdx.x, ty = threadIdx.y;                // (32, 8)
    const float* src = feat + ((size_t)b * 512 + k0) * 16384 + p0;
#pragma unroll
    for (int i = 0; i < 8; i++) {
        int kr = ty + 8 * i;
        tile[tx][kr] = __ldcs(src + (size_t)kr * 16384 + tx);
    }
    __syncthreads();
    size_t dbase = ((size_t)b * 16384 + p0) * 512 + k0;
#pragma unroll
    for (int j = 0; j < 4; j++) {
        int pr = ty + 8 * j;
        float v0 = tile[pr][2 * tx];
        float v1 = tile[pr][2 * tx + 1];
        __half h0 = __float2half_rn(v0);
        __half h1 = __float2half_rn(v1);
        __half l0 = __float2half_rn(v0 - __half2float(h0));
        __half l1 = __float2half_rn(v1 - __half2float(h1));
        size_t off = dbase + (size_t)pr * 512 + 2 * tx;
        __half2 hv = __halves2half2(h0, h1);
        __half2 lv = __halves2half2(l0, l1);
        __stcs((uint32_t*)(g_ah + off), *(uint32_t*)&hv);
        __stcs((uint32_t*)(g_al + off), *(uint32_t*)&lv);
    }
}

// -------- prep 2: weights reorder + split, centroids --------------------------
__global__ void prep_w(const float* __restrict__ wgt, const float* __restrict__ m,
                       const float* __restrict__ Nb) {
    int n = blockIdx.x;                 // n = c*16 + e
    int c = n >> 4, e = n & 15;
    const float* src = wgt + ((size_t)e * 64 + c) * 512;
    for (int k = threadIdx.x; k < 512; k += 128) {
        float v = src[k];
        __half hi = __float2half_rn(v);
        g_bh[(size_t)n * 512 + k] = hi;
        g_bl[(size_t)n * 512 + k] = __float2half_rn(v - __half2float(hi));
    }
    if (threadIdx.x == 0) g_cent[n] = m[e * 64 + c] / Nb[c];
}

// -------- stage fill (256 threads): 8 x 16B cp.async per thread ----------------
// 64B rows (4 chunks of 16B), swizzle chunk ^ ((row>>1)&3) -> ldsm conflict-free
__device__ __forceinline__ void fill_stage(uint32_t sb, int s, int kt, long P0, int n0, int t) {
    int kb = kt * BK;
    uint32_t st = sb + s * STAGE_BYTES;
    int r = t >> 2, c = t & 3;
#pragma unroll
    for (int i = 0; i < 2; i++) {
        int rr = r + i * 64;
        uint32_t d = st + rr * 64 + (uint32_t)((c ^ ((rr >> 1) & 3)) << 4);
        size_t asrc = (size_t)(P0 + rr) * 512 + kb + c * 8;
        size_t bsrc = (size_t)(n0 + rr) * 512 + kb + c * 8;
        cp16(d,           g_ah + asrc);
        cp16(d + OFF_ALO, g_al + asrc);
        cp16(d + OFF_BHI, g_bh + bsrc);
        cp16(d + OFF_BLO, g_bl + bsrc);
    }
}

// -------- main GEMM + fused RBF epilogue ---------------------------------------
__global__ __launch_bounds__(256, 2) void duq_mma(float* __restrict__ out) {
    extern __shared__ char smem[];
    uint32_t sb = smem_u32(smem);
    int t = threadIdx.x, l = t & 31, w = t >> 5;
    int nb = blockIdx.x, mb = blockIdx.y;
    long P0 = (long)mb * BM;           // 128 | 16384 -> never crosses a batch
    int n0 = nb * BN;

    if (t < BN) ((float*)(smem + CENT_OFF))[t] = g_cent[n0 + t];

    int wm = (w >> 1) * 32;            // 4 M-groups of 32
    int wn = (w & 1) * 64;             // 2 N-groups of 64

    int rl  = l & 7;                   // row within 8-row matrix
    int mh  = (l >> 3) & 1;            // matrix half bit
    int hi  = (l >> 4) & 1;            // k-chunk bit

    float acc[2][8][4];
#pragma unroll
    for (int i = 0; i < 2; i++)
#pragma unroll
        for (int j = 0; j < 8; j++)
#pragma unroll
            for (int q = 0; q < 4; q++) acc[i][j][q] = 0.0f;

    fill_stage(sb, 0, 0, P0, n0, t);
    asm volatile("cp.async.commit_group;" ::: "memory");
    fill_stage(sb, 1, 1, P0, n0, t);
    asm volatile("cp.async.commit_group;" ::: "memory");

    for (int kt = 0; kt < KTILES; kt++) {
        asm volatile("cp.async.wait_group 1;" ::: "memory");
        __syncthreads();

        if (kt + 2 < KTILES) fill_stage(sb, (kt + 2) % 3, kt + 2, P0, n0, t);
        asm volatile("cp.async.commit_group;" ::: "memory");

        uint32_t As = sb + (kt % 3) * STAGE_BYTES;
#pragma unroll
        for (int k16 = 0; k16 < 2; k16++) {
            uint32_t ah[2][4], al[2][4];
#pragma unroll
            for (int mf = 0; mf < 2; mf++) {
                int ra = wm + mf * 16 + mh * 8 + rl;
                uint32_t off = (uint32_t)(ra * 64 + (((2 * k16 + hi) ^ ((ra >> 1) & 3)) << 4));
                ldsm4(ah[mf], As + off);
                ldsm4(al[mf], As + OFF_ALO + off);
            }
#pragma unroll
            for (int np = 0; np < 4; np++) {
                int rb = wn + np * 16 + hi * 8 + rl;
                uint32_t off = (uint32_t)(rb * 64 + (((2 * k16 + mh) ^ ((rb >> 1) & 3)) << 4));
                uint32_t bh4[4], bl4[4];
                ldsm4(bh4, As + OFF_BHI + off);
                ldsm4(bl4, As + OFF_BLO + off);
                // product-major order (acc RAW distance 4)
#pragma unroll
                for (int mf = 0; mf < 2; mf++)
#pragma unroll
                    for (int h = 0; h < 2; h++)
                        mma_f32(acc[mf][2 * np + h], ah[mf], &bh4[2 * h]);
#pragma unroll
                for (int mf = 0; mf < 2; mf++)
#pragma unroll
                    for (int h = 0; h < 2; h++)
                        mma_f32(acc[mf][2 * np + h], ah[mf], &bl4[2 * h]);
#pragma unroll
                for (int mf = 0; mf < 2; mf++)
#pragma unroll
                    for (int h = 0; h < 2; h++)
                        mma_f32(acc[mf][2 * np + h], al[mf], &bh4[2 * h]);
            }
        }
    }

    // ---- epilogue: diff^2, 16-e reduction (2 quad shuffles), __expf, store ----
    const float* centS = (const float*)(smem + CENT_OFF);
    int q2 = l & 3;
    int cb = (n0 + wn) >> 4;           // first of this warp's 4 channels

#pragma unroll
    for (int mf = 0; mf < 2; mf++) {
        float s[4][2];
#pragma unroll
        for (int ch = 0; ch < 4; ch++) { s[ch][0] = 0.0f; s[ch][1] = 0.0f; }
#pragma unroll
        for (int nf = 0; nf < 8; nf++) {
            int ch = nf >> 1;
#pragma unroll
            for (int j = 0; j < 2; j++) {
                float ce = centS[wn + nf * 8 + 2 * q2 + j];
                float d0 = acc[mf][nf][j]     - ce;
                float d1 = acc[mf][nf][2 + j] - ce;
                s[ch][0] = fmaf(d0, d0, s[ch][0]);
                s[ch][1] = fmaf(d1, d1, s[ch][1]);
            }
        }
#pragma unroll
        for (int ch = 0; ch < 4; ch++)
#pragma unroll
            for (int r = 0; r < 2; r++) {
                s[ch][r] += __shfl_xor_sync(0xFFFFFFFFu, s[ch][r], 1);
                s[ch][r] += __shfl_xor_sync(0xFFFFFFFFu, s[ch][r], 2);
            }
        float v0 = (q2 == 0) ? s[0][0] : (q2 == 1) ? s[1][0] : (q2 == 2) ? s[2][0] : s[3][0];
        float v1 = (q2 == 0) ? s[0][1] : (q2 == 1) ? s[1][1] : (q2 == 2) ? s[2][1] : s[3][1];

        long gp = P0 + wm + mf * 16 + (l >> 2);
        int b   = (int)(gp >> 14);
        int pin = (int)(gp & 16383);
        int ch  = cb + q2;
        float* o = out + ((size_t)b * 64 + ch) * 16384 + pin;
        o[0] = __expf(-3.125f * v0);
        o[8] = __expf(-3.125f * v1);
    }
}

// -------- launch ----------------------------------------------------------------
extern "C" void kernel_launch(void* const* d_in, const int* in_sizes, int n_in,
                              void* d_out, int out_size)
{
    const float* feat = (const float*)d_in[0];   // [8, 512, 128, 128]
    const float* wgt  = (const float*)d_in[1];   // [16, 64, 512]
    const float* m    = (const float*)d_in[2];   // [16, 64]
    const float* N    = (const float*)d_in[3];   // [64]
    float* out        = (float*)d_out;           // [8, 64, 128, 128]

    cudaFuncSetAttribute(duq_mma, cudaFuncAttributeMaxDynamicSharedMemorySize, SMEM_TOTAL);

    prep_feat<<<dim3(512, 8, 8), dim3(32, 8)>>>(feat);
    prep_w<<<1024, 128>>>(wgt, m, N);
    duq_mma<<<dim3(8, 1024), 256, SMEM_TOTAL>>>(out);
}

// round 17
// speedup vs baseline: 1.0470x; 1.0020x over previous
#include <cuda_runtime.h>
#include <cuda_fp16.h>
#include <cstdint>
#include <math.h>

// ============================================================================
// DUQ head via HMMA 3xFP16-split GEMM — R9 mainloop (best known) + vectorized
// transpose/split prep (LDG.128 in, STG.128 out, conflict-free smem).
// out[b,c,p] = exp(-3.125 * sum_e (emb[p, c*16+e] - cent[c*16+e])^2)
// emb = feat[b,:,p].w[n,:], n=c*16+e, K=512.
// a = ah+al, b = bh+bl (exact fp16 splits); acc += ah*bh + ah*bl + al*bh (f32).
// CTA tile 128x128, warp tile 32x64 (8 warps/256 thr), BK=32,
// 3-stage cp.async, 96KB smem, 2 CTAs/SM.
// ============================================================================

#define BM 128
#define BN 128
#define BK 32
#define KTILES 16            // 512 / 32
#define STAGE_BYTES 32768    // Ahi 8K | Alo 8K | Bhi 8K | Blo 8K
#define OFF_ALO 8192
#define OFF_BHI 16384
#define OFF_BLO 24576
#define CENT_OFF (3 * STAGE_BYTES)
#define SMEM_TOTAL (CENT_OFF + 512)

// -------- device-global scratch (no cudaMalloc allowed) ----------------------
__device__ __half g_ah[67108864];   // [131072 px][512 k]
__device__ __half g_al[67108864];
__device__ __half g_bh[524288];     // [1024 n][512 k], n = c*16+e
__device__ __half g_bl[524288];
__device__ float  g_cent[1024];

// -------- helpers -------------------------------------------------------------
__device__ __forceinline__ uint32_t smem_u32(const void* p) {
    uint32_t a;
    asm("{ .reg .u64 t; cvta.to.shared.u64 t, %1; cvt.u32.u64 %0, t; }" : "=r"(a) : "l"(p));
    return a;
}
__device__ __forceinline__ void cp16(uint32_t dst, const __half* src) {
    asm volatile("cp.async.cg.shared.global [%0], [%1], 16;"
                 :: "r"(dst), "l"(__cvta_generic_to_global(src)));
}
__device__ __forceinline__ void ldsm4(uint32_t* r, uint32_t addr) {
    asm volatile("ldmatrix.sync.aligned.m8n8.x4.shared.b16 {%0,%1,%2,%3}, [%4];"
                 : "=r"(r[0]), "=r"(r[1]), "=r"(r[2]), "=r"(r[3]) : "r"(addr));
}
__device__ __forceinline__ void mma_f32(float* c, const uint32_t* a, const uint32_t* b) {
    asm volatile("mma.sync.aligned.m16n8k16.row.col.f32.f16.f16.f32 "
                 "{%0,%1,%2,%3}, {%4,%5,%6,%7}, {%8,%9}, {%0,%1,%2,%3};"
                 : "+f"(c[0]), "+f"(c[1]), "+f"(c[2]), "+f"(c[3])
                 : "r"(a[0]), "r"(a[1]), "r"(a[2]), "r"(a[3]), "r"(b[0]), "r"(b[1]));
}
__device__ __forceinline__ uint32_t pack_hi(float a, float b) {
    __half2 h = __floats2half2_rn(a, b);
    return *(uint32_t*)&h;
}

// -------- prep 1: transpose + fp16-split, fully vectorized ---------------------
// tile 32 px x 64 k. Loads: 2x LDG.128 per thread. Stores: 2x STG.128.
// smem pad 65 -> both STS (scattered) and transposed LDS are conflict-free.
__global__ void prep_feat(const float* __restrict__ feat) {
    __shared__ float tile[32][65];     // [p][k]
    int b  = blockIdx.z;
    int p0 = blockIdx.x * 32, k0 = blockIdx.y * 64;
    int t  = threadIdx.x;              // 256

    // ---- load: thread (kr = t>>3 (+32), c = t&7) reads float4 at p = 4c ----
    {
        int kr = t >> 3, c = t & 7;
        const float* src = feat + ((size_t)(b * 512 + k0 + kr)) * 16384 + p0 + 4 * c;
#pragma unroll
        for (int pass = 0; pass < 2; pass++) {
            float4 v = __ldcs((const float4*)(src + (size_t)pass * 32 * 16384));
            int kk = kr + pass * 32;
            tile[4 * c + 0][kk] = v.x;
            tile[4 * c + 1][kk] = v.y;
            tile[4 * c + 2][kk] = v.z;
            tile[4 * c + 3][kk] = v.w;
        }
    }
    __syncthreads();

    // ---- store: thread (p = t>>3, ko = (t&7)*8) writes 8 k's as hi/lo uint4 ----
    {
        int p = t >> 3, ko = (t & 7) * 8;
        float v[8];
#pragma unroll
        for (int i = 0; i < 8; i++) v[i] = tile[p][ko + i];
        uint4 H, L;
        float r[8];
        H.x = pack_hi(v[0], v[1]); H.y = pack_hi(v[2], v[3]);
        H.z = pack_hi(v[4], v[5]); H.w = pack_hi(v[6], v[7]);
        {
            __half2 h;
            h = *(__half2*)&H.x; float2 f = __half22float2(h); r[0] = v[0]-f.x; r[1] = v[1]-f.y;
            h = *(__half2*)&H.y; f = __half22float2(h);        r[2] = v[2]-f.x; r[3] = v[3]-f.y;
            h = *(__half2*)&H.z; f = __half22float2(h);        r[4] = v[4]-f.x; r[5] = v[5]-f.y;
            h = *(__half2*)&H.w; f = __half22float2(h);        r[6] = v[6]-f.x; r[7] = v[7]-f.y;
        }
        L.x = pack_hi(r[0], r[1]); L.y = pack_hi(r[2], r[3]);
        L.z = pack_hi(r[4], r[5]); L.w = pack_hi(r[6], r[7]);
        size_t off = ((size_t)b * 16384 + p0 + p) * 512 + k0 + ko;
        __stcs((uint4*)(g_ah + off), H);
        __stcs((uint4*)(g_al + off), L);
    }
}

// -------- prep 2: weights reorder + split, centroids --------------------------
__global__ void prep_w(const float* __restrict__ wgt, const float* __restrict__ m,
                       const float* __restrict__ Nb) {
    int n = blockIdx.x;                 // n = c*16 + e
    int c = n >> 4, e = n & 15;
    const float* src = wgt + ((size_t)e * 64 + c) * 512;
    for (int k = threadIdx.x; k < 512; k += 128) {
        float v = src[k];
        __half hi = __float2half_rn(v);
        g_bh[(size_t)n * 512 + k] = hi;
        g_bl[(size_t)n * 512 + k] = __float2half_rn(v - __half2float(hi));
    }
    if (threadIdx.x == 0) g_cent[n] = m[e * 64 + c] / Nb[c];
}

// -------- stage fill (256 threads): 8 x 16B cp.async per thread ----------------
// 64B rows (4 chunks of 16B), swizzle chunk ^ ((row>>1)&3) -> ldsm conflict-free
__device__ __forceinline__ void fill_stage(uint32_t sb, int s, int kt, long P0, int n0, int t) {
    int kb = kt * BK;
    uint32_t st = sb + s * STAGE_BYTES;
    int r = t >> 2, c = t & 3;
#pragma unroll
    for (int i = 0; i < 2; i++) {
        int rr = r + i * 64;
        uint32_t d = st + rr * 64 + (uint32_t)((c ^ ((rr >> 1) & 3)) << 4);
        size_t asrc = (size_t)(P0 + rr) * 512 + kb + c * 8;
        size_t bsrc = (size_t)(n0 + rr) * 512 + kb + c * 8;
        cp16(d,           g_ah + asrc);
        cp16(d + OFF_ALO, g_al + asrc);
        cp16(d + OFF_BHI, g_bh + bsrc);
        cp16(d + OFF_BLO, g_bl + bsrc);
    }
}

// -------- main GEMM + fused RBF epilogue (identical to R9) ----------------------
__global__ __launch_bounds__(256, 2) void duq_mma(float* __restrict__ out) {
    extern __shared__ char smem[];
    uint32_t sb = smem_u32(smem);
    int t = threadIdx.x, l = t & 31, w = t >> 5;
    int nb = blockIdx.x, mb = blockIdx.y;
    long P0 = (long)mb * BM;           // 128 | 16384 -> never crosses a batch
    int n0 = nb * BN;

    if (t < BN) ((float*)(smem + CENT_OFF))[t] = g_cent[n0 + t];

    int wm = (w >> 1) * 32;            // 4 M-groups of 32
    int wn = (w & 1) * 64;             // 2 N-groups of 64

    int rl  = l & 7;                   // row within 8-row matrix
    int mh  = (l >> 3) & 1;            // matrix half bit
    int hi  = (l >> 4) & 1;            // k-chunk bit

    float acc[2][8][4];
#pragma unroll
    for (int i = 0; i < 2; i++)
#pragma unroll
        for (int j = 0; j < 8; j++)
#pragma unroll
            for (int q = 0; q < 4; q++) acc[i][j][q] = 0.0f;

    fill_stage(sb, 0, 0, P0, n0, t);
    asm volatile("cp.async.commit_group;" ::: "memory");
    fill_stage(sb, 1, 1, P0, n0, t);
    asm volatile("cp.async.commit_group;" ::: "memory");

    for (int kt = 0; kt < KTILES; kt++) {
        asm volatile("cp.async.wait_group 1;" ::: "memory");
        __syncthreads();

        if (kt + 2 < KTILES) fill_stage(sb, (kt + 2) % 3, kt + 2, P0, n0, t);
        asm volatile("cp.async.commit_group;" ::: "memory");

        uint32_t As = sb + (kt % 3) * STAGE_BYTES;
#pragma unroll
        for (int k16 = 0; k16 < 2; k16++) {
            uint32_t ah[2][4], al[2][4];
#pragma unroll
            for (int mf = 0; mf < 2; mf++) {
                int ra = wm + mf * 16 + mh * 8 + rl;
                uint32_t off = (uint32_t)(ra * 64 + (((2 * k16 + hi) ^ ((ra >> 1) & 3)) << 4));
                ldsm4(ah[mf], As + off);
                ldsm4(al[mf], As + OFF_ALO + off);
            }
#pragma unroll
            for (int np = 0; np < 4; np++) {
                int rb = wn + np * 16 + hi * 8 + rl;
                uint32_t off = (uint32_t)(rb * 64 + (((2 * k16 + mh) ^ ((rb >> 1) & 3)) << 4));
                uint32_t bh4[4], bl4[4];
                ldsm4(bh4, As + OFF_BHI + off);
                ldsm4(bl4, As + OFF_BLO + off);
                // product-major order (acc RAW distance 4)
#pragma unroll
                for (int mf = 0; mf < 2; mf++)
#pragma unroll
                    for (int h = 0; h < 2; h++)
                        mma_f32(acc[mf][2 * np + h], ah[mf], &bh4[2 * h]);
#pragma unroll
                for (int mf = 0; mf < 2; mf++)
#pragma unroll
                    for (int h = 0; h < 2; h++)
                        mma_f32(acc[mf][2 * np + h], ah[mf], &bl4[2 * h]);
#pragma unroll
                for (int mf = 0; mf < 2; mf++)
#pragma unroll
                    for (int h = 0; h < 2; h++)
                        mma_f32(acc[mf][2 * np + h], al[mf], &bh4[2 * h]);
            }
        }
    }

    // ---- epilogue: diff^2, 16-e reduction (2 quad shuffles), __expf, store ----
    const float* centS = (const float*)(smem + CENT_OFF);
    int q2 = l & 3;
    int cb = (n0 + wn) >> 4;           // first of this warp's 4 channels

#pragma unroll
    for (int mf = 0; mf < 2; mf++) {
        float s[4][2];
#pragma unroll
        for (int ch = 0; ch < 4; ch++) { s[ch][0] = 0.0f; s[ch][1] = 0.0f; }
#pragma unroll
        for (int nf = 0; nf < 8; nf++) {
            int ch = nf >> 1;
#pragma unroll
            for (int j = 0; j < 2; j++) {
                float ce = centS[wn + nf * 8 + 2 * q2 + j];
                float d0 = acc[mf][nf][j]     - ce;
                float d1 = acc[mf][nf][2 + j] - ce;
                s[ch][0] = fmaf(d0, d0, s[ch][0]);
                s[ch][1] = fmaf(d1, d1, s[ch][1]);
            }
        }
#pragma unroll
        for (int ch = 0; ch < 4; ch++)
#pragma unroll
            for (int r = 0; r < 2; r++) {
                s[ch][r] += __shfl_xor_sync(0xFFFFFFFFu, s[ch][r], 1);
                s[ch][r] += __shfl_xor_sync(0xFFFFFFFFu, s[ch][r], 2);
            }
        float v0 = (q2 == 0) ? s[0][0] : (q2 == 1) ? s[1][0] : (q2 == 2) ? s[2][0] : s[3][0];
        float v1 = (q2 == 0) ? s[0][1] : (q2 == 1) ? s[1][1] : (q2 == 2) ? s[2][1] : s[3][1];

        long gp = P0 + wm + mf * 16 + (l >> 2);
        int b   = (int)(gp >> 14);
        int pin = (int)(gp & 16383);
        int ch  = cb + q2;
        float* o = out + ((size_t)b * 64 + ch) * 16384 + pin;
        o[0] = __expf(-3.125f * v0);
        o[8] = __expf(-3.125f * v1);
    }
}

// -------- launch ----------------------------------------------------------------
extern "C" void kernel_launch(void* const* d_in, const int* in_sizes, int n_in,
                              void* d_out, int out_size)
{
    const float* feat = (const float*)d_in[0];   // [8, 512, 128, 128]
    const float* wgt  = (const float*)d_in[1];   // [16, 64, 512]
    const float* m    = (const float*)d_in[2];   // [16, 64]
    const float* N    = (const float*)d_in[3];   // [64]
    float* out        = (float*)d_out;           // [8, 64, 128, 128]

    cudaFuncSetAttribute(duq_mma, cudaFuncAttributeMaxDynamicSharedMemorySize, SMEM_TOTAL);

    prep_feat<<<dim3(512, 8, 8), 256>>>(feat);
    prep_w<<<1024, 128>>>(wgt, m, N);
    duq_mma<<<dim3(8, 1024), 256, SMEM_TOTAL>>>(out);
}